// round 2
// baseline (speedup 1.0000x reference)
#include <cuda_runtime.h>
#include <cstdint>

// ---------------------------------------------------------------------------
// StochLinear: reproduce JAX threefry bitstreams exactly, then bit-packed
// XNOR-popcount GEMM.
//
//   out[b,n] = 0.5*S[b,n] - 0.25*(sA[b] + sB[n]) + 2048 + bias[n]
//   S[b,n]   = sum_{l,k} A_bit[l,b,k] * W_bit[l,k,n]
//
// Partitionable threefry semantics (JAX >= 0.4.36 default):
//   split    : foldlike, key_i = threefry(key, (0, i)) -> (o0, o1)
//   bits[n]  : threefry(key, (hi(n), lo(n))), 32-bit result = o0 ^ o1   <- R1 fix
// ---------------------------------------------------------------------------

#define JAX_PARTITIONABLE 1

#define B_DIM 4096
#define K_DIM 2048
#define N_DIM 2048
#define L_DIM 8
#define KW    (K_DIM / 32)      // 64 packed words per (l, row)
#define ROW_WORDS (L_DIM * KW)  // 512 words per packed row

// Scratch (device globals: no allocations allowed)
__device__ uint32_t g_Apack[B_DIM * ROW_WORDS]; // 8 MB
__device__ uint32_t g_Wpack[N_DIM * ROW_WORDS]; // 4 MB
__device__ int g_sA[B_DIM];
__device__ int g_sB[N_DIM];

// ---------------- Threefry-2x32 (20 rounds), host+device ----------------
__host__ __device__ __forceinline__ void tf2x32(uint32_t k0, uint32_t k1,
                                                uint32_t x0, uint32_t x1,
                                                uint32_t &o0, uint32_t &o1)
{
    uint32_t ks2 = k0 ^ k1 ^ 0x1BD11BDAu;
    x0 += k0; x1 += k1;
#define TFR(r) { x0 += x1; x1 = (x1 << (r)) | (x1 >> (32 - (r))); x1 ^= x0; }
    TFR(13) TFR(15) TFR(26) TFR(6)
    x0 += k1;  x1 += ks2 + 1u;
    TFR(17) TFR(29) TFR(16) TFR(24)
    x0 += ks2; x1 += k0 + 2u;
    TFR(13) TFR(15) TFR(26) TFR(6)
    x0 += k0;  x1 += k1 + 3u;
    TFR(17) TFR(29) TFR(16) TFR(24)
    x0 += k1;  x1 += ks2 + 4u;
    TFR(13) TFR(15) TFR(26) TFR(6)
    x0 += ks2; x1 += k0 + 5u;
#undef TFR
    o0 = x0; o1 = x1;
}

// JAX uniform: bitcast((bits>>9) | 0x3F800000) - 1.0f  ->  [0,1)
__device__ __forceinline__ float unit_f32(uint32_t bits)
{
    return __uint_as_float((bits >> 9) | 0x3F800000u) - 1.0f;
}

// ---------------- bit generation: A = to_stoch(x), shape (L,B,K) ----------
// linear idx n = (l<<23) | (b<<11) | k   (B*K = 2^23, K = 2^11); hi word = 0
__global__ void __launch_bounds__(256) gen_bits_A(const float* __restrict__ x,
                                                  uint32_t k0, uint32_t k1)
{
    int t  = threadIdx.x;
    int b  = blockIdx.x * 4 + (t >> 6);
    int kw = t & 63;
    const float* xr = x + (size_t)b * K_DIM + (size_t)kw * 32;

    uint32_t words[8] = {0,0,0,0,0,0,0,0};
    for (int j = 0; j < 32; ++j) {
        float v = xr[j];
        float p = fminf(fmaxf((v + 1.0f) * 0.5f, 0.0f), 1.0f);
        uint32_t base = ((uint32_t)b << 11) | (uint32_t)(kw * 32 + j);
#if JAX_PARTITIONABLE
#pragma unroll
        for (int l = 0; l < 8; ++l) {
            uint32_t o0, o1;
            tf2x32(k0, k1, 0u, ((uint32_t)l << 23) | base, o0, o1);
            if (unit_f32(o0 ^ o1) < p) words[l] |= (1u << j);   // <- XOR fix
        }
#else
#pragma unroll
        for (int l = 0; l < 4; ++l) {
            uint32_t n = ((uint32_t)l << 23) | base;
            uint32_t o0, o1;
            tf2x32(k0, k1, n, n + (4u << 23), o0, o1);
            if (unit_f32(o0) < p) words[l]     |= (1u << j);
            if (unit_f32(o1) < p) words[l + 4] |= (1u << j);
        }
#endif
    }
    int cnt = 0;
#pragma unroll
    for (int l = 0; l < 8; ++l) {
        g_Apack[(size_t)b * ROW_WORDS + l * KW + kw] = words[l];
        cnt += __popc(words[l]);
    }
#pragma unroll
    for (int o = 16; o > 0; o >>= 1) cnt += __shfl_down_sync(0xffffffffu, cnt, o);
    if ((t & 31) == 0) atomicAdd(&g_sA[b], cnt);
}

// ---------------- bit generation: Wb = to_stoch(weight.T), shape (L,K,N) --
// linear idx n = (l<<22) | (k<<11) | nn   (K*N = 2^22, N = 2^11); hi word = 0
// weight.T[k,nn] = weight[nn*K + k]
__global__ void __launch_bounds__(256) gen_bits_W(const float* __restrict__ w,
                                                  uint32_t k0, uint32_t k1)
{
    int t  = threadIdx.x;
    int nn = blockIdx.x * 4 + (t >> 6);
    int kw = t & 63;
    const float* wr = w + (size_t)nn * K_DIM + (size_t)kw * 32;

    uint32_t words[8] = {0,0,0,0,0,0,0,0};
    for (int j = 0; j < 32; ++j) {
        float v = wr[j];
        float p = fminf(fmaxf((v + 1.0f) * 0.5f, 0.0f), 1.0f);
        uint32_t kk = (uint32_t)(kw * 32 + j);
        uint32_t base = (kk << 11) | (uint32_t)nn;
#if JAX_PARTITIONABLE
#pragma unroll
        for (int l = 0; l < 8; ++l) {
            uint32_t o0, o1;
            tf2x32(k0, k1, 0u, ((uint32_t)l << 22) | base, o0, o1);
            if (unit_f32(o0 ^ o1) < p) words[l] |= (1u << j);   // <- XOR fix
        }
#else
#pragma unroll
        for (int l = 0; l < 4; ++l) {
            uint32_t n = ((uint32_t)l << 22) | base;
            uint32_t o0, o1;
            tf2x32(k0, k1, n, n + (4u << 22), o0, o1);
            if (unit_f32(o0) < p) words[l]     |= (1u << j);
            if (unit_f32(o1) < p) words[l + 4] |= (1u << j);
        }
#endif
    }
    int cnt = 0;
#pragma unroll
    for (int l = 0; l < 8; ++l) {
        g_Wpack[(size_t)nn * ROW_WORDS + l * KW + kw] = words[l];
        cnt += __popc(words[l]);
    }
#pragma unroll
    for (int o = 16; o > 0; o >>= 1) cnt += __shfl_down_sync(0xffffffffu, cnt, o);
    if ((t & 31) == 0) atomicAdd(&g_sB[nn], cnt);
}

__global__ void zero_counts()
{
    int i = blockIdx.x * blockDim.x + threadIdx.x;
    if (i < B_DIM) g_sA[i] = 0;
    if (i < N_DIM) g_sB[i] = 0;
}

// ---------------- bit-packed popcount GEMM + epilogue ---------------------
#define BKW 32
#define LDW 132   // 128 + 4 pad (keeps 16B alignment: 132*4 = 528 = 33*16)

__global__ void __launch_bounds__(256) popc_gemm(const float* __restrict__ bias,
                                                 float* __restrict__ out)
{
    __shared__ uint32_t As[BKW][LDW];
    __shared__ uint32_t Ws[BKW][LDW];

    int tid  = threadIdx.x;
    int row0 = blockIdx.y * 128;
    int col0 = blockIdx.x * 128;
    int tx = tid & 15;
    int ty = tid >> 4;

    int acc[8][8];
#pragma unroll
    for (int i = 0; i < 8; ++i)
#pragma unroll
        for (int j = 0; j < 8; ++j) acc[i][j] = 0;

    for (int wt = 0; wt < ROW_WORDS; wt += BKW) {
#pragma unroll
        for (int q = 0; q < 4; ++q) {
            int idx = tid + q * 256;
            int r   = idx >> 3;
            int c4  = (idx & 7) * 4;
            uint4 va = *reinterpret_cast<const uint4*>(
                &g_Apack[(size_t)(row0 + r) * ROW_WORDS + wt + c4]);
            As[c4 + 0][r] = va.x; As[c4 + 1][r] = va.y;
            As[c4 + 2][r] = va.z; As[c4 + 3][r] = va.w;
            uint4 vb = *reinterpret_cast<const uint4*>(
                &g_Wpack[(size_t)(col0 + r) * ROW_WORDS + wt + c4]);
            Ws[c4 + 0][r] = vb.x; Ws[c4 + 1][r] = vb.y;
            Ws[c4 + 2][r] = vb.z; Ws[c4 + 3][r] = vb.w;
        }
        __syncthreads();
#pragma unroll
        for (int w = 0; w < BKW; ++w) {
            uint32_t a[8], bb[8];
            *reinterpret_cast<uint4*>(&a[0])  = *reinterpret_cast<const uint4*>(&As[w][ty * 4]);
            *reinterpret_cast<uint4*>(&a[4])  = *reinterpret_cast<const uint4*>(&As[w][64 + ty * 4]);
            *reinterpret_cast<uint4*>(&bb[0]) = *reinterpret_cast<const uint4*>(&Ws[w][tx * 4]);
            *reinterpret_cast<uint4*>(&bb[4]) = *reinterpret_cast<const uint4*>(&Ws[w][64 + tx * 4]);
#pragma unroll
            for (int i = 0; i < 8; ++i)
#pragma unroll
                for (int j = 0; j < 8; ++j)
                    acc[i][j] += __popc(a[i] & bb[j]);
        }
        __syncthreads();
    }

    // out = 0.5*S - 0.25*(sA+sB) + 2048 + bias   (all exact in fp32)
#pragma unroll
    for (int i = 0; i < 8; ++i) {
        int ri = row0 + ((i < 4) ? (ty * 4 + i) : (64 + ty * 4 + (i - 4)));
        float sa = (float)g_sA[ri];
#pragma unroll
        for (int jh = 0; jh < 2; ++jh) {
            int cbase = col0 + jh * 64 + tx * 4;
            float4 o;
            float* op = reinterpret_cast<float*>(&o);
#pragma unroll
            for (int j = 0; j < 4; ++j) {
                int cj = cbase + j;
                float s = (float)acc[i][jh * 4 + j];
                op[j] = 0.5f * s - 0.25f * (sa + (float)g_sB[cj]) + 2048.0f + bias[cj];
            }
            *reinterpret_cast<float4*>(&out[(size_t)ri * N_DIM + cbase]) = o;
        }
    }
}

// ---------------------------------------------------------------------------
extern "C" void kernel_launch(void* const* d_in, const int* in_sizes, int n_in,
                              void* d_out, int out_size)
{
    const float* x    = (const float*)d_in[0];
    const float* w    = (const float*)d_in[1];
    const float* bias = (const float*)d_in[2];
    float* out        = (float*)d_out;

    // Derive kA, kB from jax.random.split(jax.random.key(42)) on the host.
    uint32_t kA0, kA1, kB0, kB1;
#if JAX_PARTITIONABLE
    tf2x32(0u, 42u, 0u, 0u, kA0, kA1);   // foldlike split: key_i = tf(key,(0,i))
    tf2x32(0u, 42u, 0u, 1u, kB0, kB1);
#else
    {   // original split: counts iota(4) -> lanes (0,2),(1,3); rows of outputs
        uint32_t y00, y10, y01, y11;
        tf2x32(0u, 42u, 0u, 2u, y00, y10);
        tf2x32(0u, 42u, 1u, 3u, y01, y11);
        kA0 = y00; kA1 = y01;
        kB0 = y10; kB1 = y11;
    }
#endif

    zero_counts<<<16, 256>>>();
    gen_bits_A<<<B_DIM / 4, 256>>>(x, kA0, kA1);
    gen_bits_W<<<N_DIM / 4, 256>>>(w, kB0, kB1);
    popc_gemm<<<dim3(N_DIM / 128, B_DIM / 128), 256>>>(bias, out);
}